// round 5
// baseline (speedup 1.0000x reference)
#include <cuda_runtime.h>
#include <cuda_bf16.h>
#include <stdint.h>

// ScaledDotProductAttention: B=2, H=16, S=2048, D=64, scale=8
#define BB 2
#define HH 16
#define SS 2048
#define DD 64
#define QB 128            // q rows per CTA
#define NC 128            // k cols per chunk
#define NCHUNK (SS / NC)  // 16
#define NTHR 512          // 16 warps: 8 q-groups x 2 col-halves

#define STRB 144                 // smem row stride bytes (72 bf16, ldmatrix conflict-free)
#define TILEB (128 * STRB)       // 18432 B per [128 x 64] bf16 tile
#define OFF_QH 0
#define OFF_QL (1 * TILEB)
#define OFF_KH (2 * TILEB)
#define OFF_KL (3 * TILEB)
#define OFF_VH (4 * TILEB)
#define OFF_VL (5 * TILEB)
#define OFF_MSK (6 * TILEB)
#define OFF_L2  (OFF_MSK + SS * 4)      // float l2[128][2] partial row sums
#define SMEM_TOTAL (OFF_L2 + 128 * 2 * 4)   // 119808 B

__device__ __forceinline__ uint32_t s2u(const void* p) {
    uint32_t a;
    asm("{ .reg .u64 t; cvta.to.shared.u64 t, %1; cvt.u32.u64 %0, t; }" : "=r"(a) : "l"(p));
    return a;
}
__device__ __forceinline__ void ldsm4(uint32_t r[4], uint32_t a) {
    asm volatile("ldmatrix.sync.aligned.m8n8.x4.shared.b16 {%0,%1,%2,%3}, [%4];"
                 : "=r"(r[0]), "=r"(r[1]), "=r"(r[2]), "=r"(r[3]) : "r"(a));
}
__device__ __forceinline__ void ldsm4t(uint32_t r[4], uint32_t a) {
    asm volatile("ldmatrix.sync.aligned.m8n8.x4.trans.shared.b16 {%0,%1,%2,%3}, [%4];"
                 : "=r"(r[0]), "=r"(r[1]), "=r"(r[2]), "=r"(r[3]) : "r"(a));
}
__device__ __forceinline__ void mmab(float c[4], const uint32_t a[4], uint32_t b0, uint32_t b1) {
    asm volatile("mma.sync.aligned.m16n8k16.row.col.f32.bf16.bf16.f32 "
                 "{%0,%1,%2,%3}, {%4,%5,%6,%7}, {%8,%9}, {%0,%1,%2,%3};"
                 : "+f"(c[0]), "+f"(c[1]), "+f"(c[2]), "+f"(c[3])
                 : "r"(a[0]), "r"(a[1]), "r"(a[2]), "r"(a[3]), "r"(b0), "r"(b1));
}
__device__ __forceinline__ uint32_t pkbf(__nv_bfloat16 a, __nv_bfloat16 b) {
    __nv_bfloat162 t(a, b);
    return *(uint32_t*)&t;
}

// load [128 x 64] fp32 tile row-major -> bf16 hi/lo tiles in smem (stride 144B)
__device__ __forceinline__ void conv_tile(const float* __restrict__ g, char* sm,
                                          int offH, int offL, int tid, float scale)
{
    #pragma unroll
    for (int it = 0; it < 4; it++) {
        int lin = tid + it * NTHR;
        int r = lin >> 4, d4 = (lin & 15) << 2;
        float4 x = *(const float4*)&g[r * DD + d4];
        x.x *= scale; x.y *= scale; x.z *= scale; x.w *= scale;
        __nv_bfloat16 h0 = __float2bfloat16(x.x), h1 = __float2bfloat16(x.y);
        __nv_bfloat16 h2 = __float2bfloat16(x.z), h3 = __float2bfloat16(x.w);
        float l0 = x.x - __bfloat162float(h0), l1 = x.y - __bfloat162float(h1);
        float l2 = x.z - __bfloat162float(h2), l3 = x.w - __bfloat162float(h3);
        int off = r * STRB + d4 * 2;
        *(uint2*)(sm + offH + off) = make_uint2(pkbf(h0, h1), pkbf(h2, h3));
        *(uint2*)(sm + offL + off) =
            make_uint2(pkbf(__float2bfloat16(l0), __float2bfloat16(l1)),
                       pkbf(__float2bfloat16(l2), __float2bfloat16(l3)));
    }
}

// S for this warp's 16 rows x 64-col half: acc[8 n-tiles][4], 3-term bf16
__device__ __forceinline__ void compute_S_half(float acc[8][4], uint32_t sb,
                                               uint32_t aoff, uint32_t koff)
{
    #pragma unroll
    for (int j = 0; j < 8; j++)
        #pragma unroll
        for (int i = 0; i < 4; i++) acc[j][i] = 0.0f;
    #pragma unroll
    for (int s = 0; s < 4; s++) {
        uint32_t aH[4], aL[4];
        ldsm4(aH, sb + OFF_QH + aoff + s * 32);
        ldsm4(aL, sb + OFF_QL + aoff + s * 32);
        #pragma unroll
        for (int jp = 0; jp < 4; jp++) {
            uint32_t bH[4], bL[4];
            ldsm4(bH, sb + OFF_KH + koff + jp * (16 * STRB) + s * 32);
            ldsm4(bL, sb + OFF_KL + koff + jp * (16 * STRB) + s * 32);
            mmab(acc[2 * jp],     aH, bH[0], bH[1]);
            mmab(acc[2 * jp + 1], aH, bH[2], bH[3]);
            mmab(acc[2 * jp],     aH, bL[0], bL[1]);
            mmab(acc[2 * jp + 1], aH, bL[2], bL[3]);
            mmab(acc[2 * jp],     aL, bH[0], bH[1]);
            mmab(acc[2 * jp + 1], aL, bH[2], bH[3]);
        }
    }
}

__global__ __launch_bounds__(NTHR, 1)
void fa_mma_kernel(const float* __restrict__ Q, const float* __restrict__ K,
                   const float* __restrict__ V, const int* __restrict__ mask,
                   float* __restrict__ out_o, float* __restrict__ out_p)
{
    extern __shared__ char sm[];
    const uint32_t sb = s2u(sm);
    const int tid = threadIdx.x, wid = tid >> 5, lane = tid & 31;
    const int qg = wid & 7, cg = wid >> 3;
    const int q0 = qg * 16;

    const int qtile = blockIdx.x, h = blockIdx.y, b = blockIdx.z;
    const long bh = (long)(b * HH + h);
    const long qbase = bh * SS + (long)qtile * QB;
    const float* Qp = Q + qbase * DD;
    const float* Kp = K + bh * SS * DD;
    const float* Vp = V + bh * SS * DD;

    int* msk = (int*)(sm + OFF_MSK);
    for (int i = tid; i < SS; i += NTHR) msk[i] = mask[(long)b * SS + i];
    conv_tile(Qp, sm, OFF_QH, OFF_QL, tid, 0.125f);

    const uint32_t kbase = (uint32_t)cg * 64 * STRB;
    const uint32_t aoff = (uint32_t)(q0 + (lane & 15)) * STRB + ((lane >> 4) & 1) * 16;
    const uint32_t koff = kbase + (uint32_t)((lane & 7) + ((lane & 16) ? 8 : 0)) * STRB
                        + ((lane & 8) ? 16 : 0);
    const uint32_t voff = kbase + (uint32_t)(lane & 15) * STRB + ((lane >> 4) & 1) * 16;

    float oacc[8][4];
    #pragma unroll
    for (int j = 0; j < 8; j++)
        #pragma unroll
        for (int i = 0; i < 4; i++) oacc[j][i] = 0.0f;
    float rs0 = 0.0f, rs1 = 0.0f;

    // ================= Pass 1: partial rowsums + partial O over this warp's k-half ======
    for (int ch = 0; ch < NCHUNK; ch++) {
        __syncthreads();
        conv_tile(Kp + (long)ch * NC * DD, sm, OFF_KH, OFF_KL, tid, 1.0f);
        conv_tile(Vp + (long)ch * NC * DD, sm, OFF_VH, OFF_VL, tid, 1.0f);
        __syncthreads();

        float acc[8][4];
        compute_S_half(acc, sb, aoff, koff);

        uint32_t PH[4][4], PL[4][4];
        #pragma unroll
        for (int jt = 0; jt < 8; jt++) {
            int colb = ch * NC + cg * 64 + 8 * jt + 2 * (lane & 3);
            int2 mm = *(const int2*)&msk[colb];
            float m0 = mm.x ? 1.0f : 0.0f, m1 = mm.y ? 1.0f : 0.0f;
            float e0 = __expf(acc[jt][0]) * m0, e1 = __expf(acc[jt][1]) * m1;
            float e2 = __expf(acc[jt][2]) * m0, e3 = __expf(acc[jt][3]) * m1;
            rs0 += e0 + e1; rs1 += e2 + e3;
            __nv_bfloat16 h0 = __float2bfloat16(e0), h1 = __float2bfloat16(e1);
            __nv_bfloat16 h2 = __float2bfloat16(e2), h3 = __float2bfloat16(e3);
            float l0 = e0 - __bfloat162float(h0), l1 = e1 - __bfloat162float(h1);
            float l2 = e2 - __bfloat162float(h2), l3 = e3 - __bfloat162float(h3);
            int s = jt >> 1, o = (jt & 1) * 2;
            PH[s][o]     = pkbf(h0, h1);
            PH[s][o + 1] = pkbf(h2, h3);
            PL[s][o]     = pkbf(__float2bfloat16(l0), __float2bfloat16(l1));
            PL[s][o + 1] = pkbf(__float2bfloat16(l2), __float2bfloat16(l3));
        }

        #pragma unroll
        for (int s = 0; s < 4; s++) {
            #pragma unroll
            for (int dp = 0; dp < 4; dp++) {
                uint32_t vH[4], vL[4];
                ldsm4t(vH, sb + OFF_VH + voff + s * (16 * STRB) + dp * 32);
                ldsm4t(vL, sb + OFF_VL + voff + s * (16 * STRB) + dp * 32);
                mmab(oacc[2 * dp],     PH[s], vH[0], vH[1]);
                mmab(oacc[2 * dp + 1], PH[s], vH[2], vH[3]);
                mmab(oacc[2 * dp],     PH[s], vL[0], vL[1]);
                mmab(oacc[2 * dp + 1], PH[s], vL[2], vL[3]);
                mmab(oacc[2 * dp],     PL[s], vH[0], vH[1]);
                mmab(oacc[2 * dp + 1], PL[s], vH[2], vH[3]);
            }
        }
    }

    // ---- row sums: intra-warp then cross-half via smem ----
    rs0 += __shfl_xor_sync(0xffffffffu, rs0, 1);
    rs0 += __shfl_xor_sync(0xffffffffu, rs0, 2);
    rs1 += __shfl_xor_sync(0xffffffffu, rs1, 1);
    rs1 += __shfl_xor_sync(0xffffffffu, rs1, 2);
    float* l2p = (float*)(sm + OFF_L2);
    __syncthreads();   // pass-1 compute fully done before reusing any smem
    if ((lane & 3) == 0) {
        l2p[2 * (q0 + (lane >> 2)) + cg]     = rs0;
        l2p[2 * (q0 + 8 + (lane >> 2)) + cg] = rs1;
    }
    __syncthreads();
    const float il0 = 1.0f / (l2p[2 * (q0 + (lane >> 2))] + l2p[2 * (q0 + (lane >> 2)) + 1]);
    const float il1 = 1.0f / (l2p[2 * (q0 + 8 + (lane >> 2))] + l2p[2 * (q0 + 8 + (lane >> 2)) + 1]);

    // ---- O cross-half reduction through smem stage (reuses K tile region) ----
    float* stg = (float*)(sm + OFF_KH);   // [128 rows][64 cols] fp32 = 32KB
    const int rlo = qg * 16 + (lane >> 2), rhi = rlo + 8;
    if (cg == 1) {
        #pragma unroll
        for (int nt = 0; nt < 8; nt++) {
            int c = 8 * nt + 2 * (lane & 3);
            *(float2*)&stg[rlo * 64 + c] = make_float2(oacc[nt][0], oacc[nt][1]);
            *(float2*)&stg[rhi * 64 + c] = make_float2(oacc[nt][2], oacc[nt][3]);
        }
    }
    __syncthreads();
    const long row0 = qbase + q0 + (lane >> 2);
    if (cg == 0) {
        #pragma unroll
        for (int nt = 0; nt < 8; nt++) {
            int c = 8 * nt + 2 * (lane & 3);
            float2 s0 = *(const float2*)&stg[rlo * 64 + c];
            float2 s1 = *(const float2*)&stg[rhi * 64 + c];
            *(float2*)&out_o[row0 * DD + c] =
                make_float2((oacc[nt][0] + s0.x) * il0, (oacc[nt][1] + s0.y) * il0);
            *(float2*)&out_o[(row0 + 8) * DD + c] =
                make_float2((oacc[nt][2] + s1.x) * il1, (oacc[nt][3] + s1.y) * il1);
        }
    }

    // ================= Pass 2: recompute S, write normalized probs =================
    for (int ch = 0; ch < NCHUNK; ch++) {
        __syncthreads();
        conv_tile(Kp + (long)ch * NC * DD, sm, OFF_KH, OFF_KL, tid, 1.0f);
        __syncthreads();

        float acc[8][4];
        compute_S_half(acc, sb, aoff, koff);

        #pragma unroll
        for (int jt = 0; jt < 8; jt++) {
            int colb = ch * NC + cg * 64 + 8 * jt + 2 * (lane & 3);
            int2 mm = *(const int2*)&msk[colb];
            float m0 = mm.x ? il0 : 0.0f, m1 = mm.y ? il0 : 0.0f;
            float n0 = mm.x ? il1 : 0.0f, n1 = mm.y ? il1 : 0.0f;
            *(float2*)&out_p[row0 * SS + colb] =
                make_float2(__expf(acc[jt][0]) * m0, __expf(acc[jt][1]) * m1);
            *(float2*)&out_p[(row0 + 8) * SS + colb] =
                make_float2(__expf(acc[jt][2]) * n0, __expf(acc[jt][3]) * n1);
        }
    }
}

extern "C" void kernel_launch(void* const* d_in, const int* in_sizes, int n_in,
                              void* d_out, int out_size)
{
    const float* Q    = (const float*)d_in[0];
    const float* K    = (const float*)d_in[1];
    const float* V    = (const float*)d_in[2];
    const int*   mask = (const int*)d_in[3];

    float* out_o = (float*)d_out;                       // [B,H,S,D]
    float* out_p = out_o + (size_t)BB * HH * SS * DD;   // [B,H,S,S]

    cudaFuncSetAttribute(fa_mma_kernel,
                         cudaFuncAttributeMaxDynamicSharedMemorySize, SMEM_TOTAL);

    dim3 grid(SS / QB, HH, BB);   // (16, 16, 2) = 512 CTAs
    fa_mma_kernel<<<grid, NTHR, SMEM_TOTAL>>>(Q, K, V, mask, out_o, out_p);
}

// round 6
// speedup vs baseline: 1.1642x; 1.1642x over previous
#include <cuda_runtime.h>
#include <cuda_bf16.h>
#include <stdint.h>

// ScaledDotProductAttention: B=2, H=16, S=2048, D=64, scale=8
#define BB 2
#define HH 16
#define SS 2048
#define DD 64
#define QB 128            // q rows per CTA
#define NC 128            // k cols per chunk
#define NCHUNK (SS / NC)  // 16
#define NTHR 512          // 16 warps: 8 q-groups x 2 col-halves
#define NELEM (BB * HH * SS * DD)   // 4,194,304

#define STRB 144                 // smem row stride bytes (72 bf16, ldmatrix conflict-free)
#define TILEB (128 * STRB)       // 18432 B per [128 x 64] bf16 tile
#define TILE_CHUNKS 1024         // 16B chunks per tile (128 rows x 8)

#define OFF_QH 0
#define OFF_QL TILEB
#define OFF_STAGE (2 * TILEB)                 // 8 tiles: stage{0,1} x {KH,KL,VH,VL}
#define ST_OFF(st, t) (OFF_STAGE + ((st) * 4 + (t)) * TILEB)
#define OFF_OST (OFF_STAGE + 2 * TILEB)       // O fp32 stage (32KB) over VH0+VL0
#define OFF_MSK (OFF_STAGE + 8 * TILEB)       // int[2048]
#define OFF_L2  (OFF_MSK + SS * 4)            // float[128][2]
#define SMEM_TOTAL (OFF_L2 + 128 * 2 * 4)     // 193536 B

// pre-converted bf16 hi/lo tensors (Q pre-scaled by 1/8)
__device__ __nv_bfloat16 g_qh[NELEM], g_ql[NELEM];
__device__ __nv_bfloat16 g_kh[NELEM], g_kl[NELEM];
__device__ __nv_bfloat16 g_vh[NELEM], g_vl[NELEM];

__device__ __forceinline__ uint32_t s2u(const void* p) {
    uint32_t a;
    asm("{ .reg .u64 t; cvta.to.shared.u64 t, %1; cvt.u32.u64 %0, t; }" : "=r"(a) : "l"(p));
    return a;
}
__device__ __forceinline__ void ldsm4(uint32_t r[4], uint32_t a) {
    asm volatile("ldmatrix.sync.aligned.m8n8.x4.shared.b16 {%0,%1,%2,%3}, [%4];"
                 : "=r"(r[0]), "=r"(r[1]), "=r"(r[2]), "=r"(r[3]) : "r"(a));
}
__device__ __forceinline__ void ldsm4t(uint32_t r[4], uint32_t a) {
    asm volatile("ldmatrix.sync.aligned.m8n8.x4.trans.shared.b16 {%0,%1,%2,%3}, [%4];"
                 : "=r"(r[0]), "=r"(r[1]), "=r"(r[2]), "=r"(r[3]) : "r"(a));
}
__device__ __forceinline__ void mmab(float c[4], const uint32_t a[4], uint32_t b0, uint32_t b1) {
    asm volatile("mma.sync.aligned.m16n8k16.row.col.f32.bf16.bf16.f32 "
                 "{%0,%1,%2,%3}, {%4,%5,%6,%7}, {%8,%9}, {%0,%1,%2,%3};"
                 : "+f"(c[0]), "+f"(c[1]), "+f"(c[2]), "+f"(c[3])
                 : "r"(a[0]), "r"(a[1]), "r"(a[2]), "r"(a[3]), "r"(b0), "r"(b1));
}
__device__ __forceinline__ uint32_t pkbf(__nv_bfloat16 a, __nv_bfloat16 b) {
    __nv_bfloat162 t(a, b);
    return *(uint32_t*)&t;
}
#define CPA16(dst, src) \
    asm volatile("cp.async.cg.shared.global [%0], [%1], 16;" :: "r"(dst), "l"(src) : "memory")
#define CPA_COMMIT() asm volatile("cp.async.commit_group;" ::: "memory")
#define CPA_WAIT0()  asm volatile("cp.async.wait_group 0;" ::: "memory")

// ---- pre-pass: fp32 -> bf16 hi/lo split for Q (scaled), K, V ----
__device__ __forceinline__ void split4(float4 x, uint2& hi, uint2& lo) {
    __nv_bfloat16 h0 = __float2bfloat16(x.x), h1 = __float2bfloat16(x.y);
    __nv_bfloat16 h2 = __float2bfloat16(x.z), h3 = __float2bfloat16(x.w);
    hi = make_uint2(pkbf(h0, h1), pkbf(h2, h3));
    lo = make_uint2(pkbf(__float2bfloat16(x.x - __bfloat162float(h0)),
                         __float2bfloat16(x.y - __bfloat162float(h1))),
                    pkbf(__float2bfloat16(x.z - __bfloat162float(h2)),
                         __float2bfloat16(x.w - __bfloat162float(h3))));
}
__global__ void convert_kernel(const float* __restrict__ Q, const float* __restrict__ K,
                               const float* __restrict__ V)
{
    long i = (long)blockIdx.x * blockDim.x + threadIdx.x;   // over NELEM/4 float4s
    if (i >= NELEM / 4) return;
    long e = i * 4;
    uint2 hi, lo;
    float4 q = *(const float4*)&Q[e];
    q.x *= 0.125f; q.y *= 0.125f; q.z *= 0.125f; q.w *= 0.125f;
    split4(q, hi, lo);
    *(uint2*)&g_qh[e] = hi; *(uint2*)&g_ql[e] = lo;
    split4(*(const float4*)&K[e], hi, lo);
    *(uint2*)&g_kh[e] = hi; *(uint2*)&g_kl[e] = lo;
    split4(*(const float4*)&V[e], hi, lo);
    *(uint2*)&g_vh[e] = hi; *(uint2*)&g_vl[e] = lo;
}

// cp.async a [128 x 64] bf16 tile (gmem row-major) into stride-144 smem
__device__ __forceinline__ void cpa_tile(uint32_t dstbase, const __nv_bfloat16* src, int tid) {
    #pragma unroll
    for (int i = tid; i < TILE_CHUNKS; i += NTHR) {
        int r = i >> 3, c8 = i & 7;
        CPA16(dstbase + r * STRB + c8 * 16, src + (long)r * DD + c8 * 8);
    }
}

// S for this warp's 16 rows x 64-col half: acc[8 n-tiles][4], 3-term bf16
__device__ __forceinline__ void compute_S_half(float acc[8][4], uint32_t qhA, uint32_t qlA,
                                               uint32_t khB, uint32_t klB)
{
    #pragma unroll
    for (int j = 0; j < 8; j++)
        #pragma unroll
        for (int i = 0; i < 4; i++) acc[j][i] = 0.0f;
    #pragma unroll
    for (int s = 0; s < 4; s++) {
        uint32_t aH[4], aL[4];
        ldsm4(aH, qhA + s * 32);
        ldsm4(aL, qlA + s * 32);
        #pragma unroll
        for (int jp = 0; jp < 4; jp++) {
            uint32_t bH[4], bL[4];
            ldsm4(bH, khB + jp * (16 * STRB) + s * 32);
            ldsm4(bL, klB + jp * (16 * STRB) + s * 32);
            mmab(acc[2 * jp],     aH, bH[0], bH[1]);
            mmab(acc[2 * jp + 1], aH, bH[2], bH[3]);
            mmab(acc[2 * jp],     aH, bL[0], bL[1]);
            mmab(acc[2 * jp + 1], aH, bL[2], bL[3]);
            mmab(acc[2 * jp],     aL, bH[0], bH[1]);
            mmab(acc[2 * jp + 1], aL, bH[2], bH[3]);
        }
    }
}

__global__ __launch_bounds__(NTHR, 1)
void fa_mma_kernel(const int* __restrict__ mask,
                   float* __restrict__ out_o, float* __restrict__ out_p)
{
    extern __shared__ char sm[];
    const uint32_t sb = s2u(sm);
    const int tid = threadIdx.x, wid = tid >> 5, lane = tid & 31;
    const int qg = wid & 7, cg = wid >> 3;
    const int q0 = qg * 16;

    const int qtile = blockIdx.x, h = blockIdx.y, b = blockIdx.z;
    const long bh = (long)(b * HH + h);
    const long qbase = bh * SS + (long)qtile * QB;
    const long kvbase = bh * SS;

    // ---- prologue: Q tiles + mask + chunk 0, one cp.async group ----
    cpa_tile(sb + OFF_QH, g_qh + qbase * DD, tid);
    cpa_tile(sb + OFF_QL, g_ql + qbase * DD, tid);
    if (tid < 512) CPA16(sb + OFF_MSK + tid * 16, mask + (long)b * SS + tid * 4);
    cpa_tile(sb + ST_OFF(0, 0), g_kh + kvbase * DD, tid);
    cpa_tile(sb + ST_OFF(0, 1), g_kl + kvbase * DD, tid);
    cpa_tile(sb + ST_OFF(0, 2), g_vh + kvbase * DD, tid);
    cpa_tile(sb + ST_OFF(0, 3), g_vl + kvbase * DD, tid);
    CPA_COMMIT();

    // per-lane ldmatrix addresses
    const uint32_t kbase = (uint32_t)cg * 64 * STRB;
    const uint32_t aoff = (uint32_t)(q0 + (lane & 15)) * STRB + ((lane >> 4) & 1) * 16;
    const uint32_t koff = kbase + (uint32_t)((lane & 7) + ((lane & 16) ? 8 : 0)) * STRB
                        + ((lane & 8) ? 16 : 0);
    const uint32_t voff = kbase + (uint32_t)(lane & 15) * STRB + ((lane >> 4) & 1) * 16;

    int* msk = (int*)(sm + OFF_MSK);
    float oacc[8][4];
    #pragma unroll
    for (int j = 0; j < 8; j++)
        #pragma unroll
        for (int i = 0; i < 4; i++) oacc[j][i] = 0.0f;
    float rs0 = 0.0f, rs1 = 0.0f;

    // ================= Pass 1: partial rowsums + partial O =================
    for (int ch = 0; ch < NCHUNK; ch++) {
        const int st = ch & 1;
        CPA_WAIT0();
        __syncthreads();   // chunk ch visible; all warps done with stage st from ch-2
        if (ch + 1 < NCHUNK) {
            const long nb = (kvbase + (long)(ch + 1) * NC) * DD;
            const int ns = st ^ 1;
            cpa_tile(sb + ST_OFF(ns, 0), g_kh + nb, tid);
            cpa_tile(sb + ST_OFF(ns, 1), g_kl + nb, tid);
            cpa_tile(sb + ST_OFF(ns, 2), g_vh + nb, tid);
            cpa_tile(sb + ST_OFF(ns, 3), g_vl + nb, tid);
            CPA_COMMIT();
        }

        float acc[8][4];
        compute_S_half(acc, sb + OFF_QH + aoff, sb + OFF_QL + aoff,
                       sb + ST_OFF(st, 0) + koff, sb + ST_OFF(st, 1) + koff);

        uint32_t PH[4][4], PL[4][4];
        #pragma unroll
        for (int jt = 0; jt < 8; jt++) {
            int colb = ch * NC + cg * 64 + 8 * jt + 2 * (lane & 3);
            int2 mm = *(const int2*)&msk[colb];
            float m0 = mm.x ? 1.0f : 0.0f, m1 = mm.y ? 1.0f : 0.0f;
            float e0 = __expf(acc[jt][0]) * m0, e1 = __expf(acc[jt][1]) * m1;
            float e2 = __expf(acc[jt][2]) * m0, e3 = __expf(acc[jt][3]) * m1;
            rs0 += e0 + e1; rs1 += e2 + e3;
            __nv_bfloat16 h0 = __float2bfloat16(e0), h1 = __float2bfloat16(e1);
            __nv_bfloat16 h2 = __float2bfloat16(e2), h3 = __float2bfloat16(e3);
            float l0 = e0 - __bfloat162float(h0), l1 = e1 - __bfloat162float(h1);
            float l2 = e2 - __bfloat162float(h2), l3 = e3 - __bfloat162float(h3);
            int s = jt >> 1, o = (jt & 1) * 2;
            PH[s][o]     = pkbf(h0, h1);
            PH[s][o + 1] = pkbf(h2, h3);
            PL[s][o]     = pkbf(__float2bfloat16(l0), __float2bfloat16(l1));
            PL[s][o + 1] = pkbf(__float2bfloat16(l2), __float2bfloat16(l3));
        }

        const uint32_t vh = sb + ST_OFF(st, 2) + voff, vl = sb + ST_OFF(st, 3) + voff;
        #pragma unroll
        for (int s = 0; s < 4; s++) {
            #pragma unroll
            for (int dp = 0; dp < 4; dp++) {
                uint32_t vH[4], vL[4];
                ldsm4t(vH, vh + s * (16 * STRB) + dp * 32);
                ldsm4t(vL, vl + s * (16 * STRB) + dp * 32);
                mmab(oacc[2 * dp],     PH[s], vH[0], vH[1]);
                mmab(oacc[2 * dp + 1], PH[s], vH[2], vH[3]);
                mmab(oacc[2 * dp],     PH[s], vL[0], vL[1]);
                mmab(oacc[2 * dp + 1], PH[s], vL[2], vL[3]);
                mmab(oacc[2 * dp],     PL[s], vH[0], vH[1]);
                mmab(oacc[2 * dp + 1], PL[s], vH[2], vH[3]);
            }
        }
    }

    __syncthreads();   // all pass-1 compute done (stages free)

    // prefetch pass-2 chunk 0 (KH0/KL0) — overlaps rowsum + O reduction
    cpa_tile(sb + ST_OFF(0, 0), g_kh + kvbase * DD, tid);
    cpa_tile(sb + ST_OFF(0, 1), g_kl + kvbase * DD, tid);
    CPA_COMMIT();

    // ---- row sums: intra-warp then cross-half via smem ----
    rs0 += __shfl_xor_sync(0xffffffffu, rs0, 1);
    rs0 += __shfl_xor_sync(0xffffffffu, rs0, 2);
    rs1 += __shfl_xor_sync(0xffffffffu, rs1, 1);
    rs1 += __shfl_xor_sync(0xffffffffu, rs1, 2);
    float* l2p = (float*)(sm + OFF_L2);
    if ((lane & 3) == 0) {
        l2p[2 * (q0 + (lane >> 2)) + cg]     = rs0;
        l2p[2 * (q0 + 8 + (lane >> 2)) + cg] = rs1;
    }
    __syncthreads();
    const float il0 = 1.0f / (l2p[2 * (q0 + (lane >> 2))] + l2p[2 * (q0 + (lane >> 2)) + 1]);
    const float il1 = 1.0f / (l2p[2 * (q0 + 8 + (lane >> 2))] + l2p[2 * (q0 + 8 + (lane >> 2)) + 1]);

    // ---- O cross-half reduction through fp32 stage (VH0/VL0 region) ----
    float* stg = (float*)(sm + OFF_OST);
    const int rlo = q0 + (lane >> 2), rhi = rlo + 8;
    if (cg == 1) {
        #pragma unroll
        for (int nt = 0; nt < 8; nt++) {
            int c = 8 * nt + 2 * (lane & 3);
            *(float2*)&stg[rlo * 64 + c] = make_float2(oacc[nt][0], oacc[nt][1]);
            *(float2*)&stg[rhi * 64 + c] = make_float2(oacc[nt][2], oacc[nt][3]);
        }
    }
    __syncthreads();
    const long row0 = qbase + q0 + (lane >> 2);
    if (cg == 0) {
        #pragma unroll
        for (int nt = 0; nt < 8; nt++) {
            int c = 8 * nt + 2 * (lane & 3);
            float2 s0 = *(const float2*)&stg[rlo * 64 + c];
            float2 s1 = *(const float2*)&stg[rhi * 64 + c];
            *(float2*)&out_o[row0 * DD + c] =
                make_float2((oacc[nt][0] + s0.x) * il0, (oacc[nt][1] + s0.y) * il0);
            *(float2*)&out_o[(row0 + 8) * DD + c] =
                make_float2((oacc[nt][2] + s1.x) * il1, (oacc[nt][3] + s1.y) * il1);
        }
    }

    // ================= Pass 2: recompute S, write normalized probs =================
    for (int ch = 0; ch < NCHUNK; ch++) {
        const int st = ch & 1;
        CPA_WAIT0();
        __syncthreads();
        if (ch + 1 < NCHUNK) {
            const long nb = (kvbase + (long)(ch + 1) * NC) * DD;
            const int ns = st ^ 1;
            cpa_tile(sb + ST_OFF(ns, 0), g_kh + nb, tid);
            cpa_tile(sb + ST_OFF(ns, 1), g_kl + nb, tid);
            CPA_COMMIT();
        }

        float acc[8][4];
        compute_S_half(acc, sb + OFF_QH + aoff, sb + OFF_QL + aoff,
                       sb + ST_OFF(st, 0) + koff, sb + ST_OFF(st, 1) + koff);

        #pragma unroll
        for (int jt = 0; jt < 8; jt++) {
            int colb = ch * NC + cg * 64 + 8 * jt + 2 * (lane & 3);
            int2 mm = *(const int2*)&msk[colb];
            float m0 = mm.x ? il0 : 0.0f, m1 = mm.y ? il0 : 0.0f;
            float n0 = mm.x ? il1 : 0.0f, n1 = mm.y ? il1 : 0.0f;
            *(float2*)&out_p[row0 * SS + colb] =
                make_float2(__expf(acc[jt][0]) * m0, __expf(acc[jt][1]) * m1);
            *(float2*)&out_p[(row0 + 8) * SS + colb] =
                make_float2(__expf(acc[jt][2]) * n0, __expf(acc[jt][3]) * n1);
        }
    }
}

extern "C" void kernel_launch(void* const* d_in, const int* in_sizes, int n_in,
                              void* d_out, int out_size)
{
    const float* Q    = (const float*)d_in[0];
    const float* K    = (const float*)d_in[1];
    const float* V    = (const float*)d_in[2];
    const int*   mask = (const int*)d_in[3];

    float* out_o = (float*)d_out;                       // [B,H,S,D]
    float* out_p = out_o + (size_t)BB * HH * SS * DD;   // [B,H,S,S]

    convert_kernel<<<NELEM / 4 / 256, 256>>>(Q, K, V);

    cudaFuncSetAttribute(fa_mma_kernel,
                         cudaFuncAttributeMaxDynamicSharedMemorySize, SMEM_TOTAL);
    dim3 grid(SS / QB, HH, BB);   // (16, 16, 2) = 512 CTAs
    fa_mma_kernel<<<grid, NTHR, SMEM_TOTAL>>>(mask, out_o, out_p);
}

// round 7
// speedup vs baseline: 1.1646x; 1.0003x over previous
#include <cuda_runtime.h>
#include <cuda_bf16.h>
#include <stdint.h>

// ScaledDotProductAttention: B=2, H=16, S=2048, D=64, scale=8
#define BB 2
#define HH 16
#define SS 2048
#define DD 64
#define QB 128            // q rows per CTA
#define NC 128            // k cols per chunk
#define NCHUNK (SS / NC)  // 16
#define NTHR 512          // 16 warps: 8 q-groups x 2 col-halves
#define NELEM (BB * HH * SS * DD)   // 4,194,304

#define STRB 144                 // smem row stride bytes (72 bf16, ldmatrix conflict-free)
#define TILEB (128 * STRB)       // 18432 B per [128 x 64] bf16 tile
#define TILE_CHUNKS 1024         // 16B chunks per tile (128 rows x 8)

#define OFF_QH 0
#define OFF_QL TILEB
#define OFF_STAGE (2 * TILEB)                 // 8 tiles: stage{0,1} x {KH,KL,VH,VL}
#define ST_OFF(st, t) (OFF_STAGE + ((st) * 4 + (t)) * TILEB)
#define OFF_OST (OFF_STAGE + 2 * TILEB)       // O fp32 stage (32KB) over VH0+VL0
#define OFF_MSK (OFF_STAGE + 8 * TILEB)       // int[2048]
#define OFF_L2  (OFF_MSK + SS * 4)            // float[128][2]
#define SMEM_TOTAL (OFF_L2 + 128 * 2 * 4)     // 193536 B

// pre-converted bf16 hi/lo tensors (Q pre-scaled by 1/8)
__device__ __nv_bfloat16 g_qh[NELEM], g_ql[NELEM];
__device__ __nv_bfloat16 g_kh[NELEM], g_kl[NELEM];
__device__ __nv_bfloat16 g_vh[NELEM], g_vl[NELEM];

__device__ __forceinline__ uint32_t s2u(const void* p) {
    uint32_t a;
    asm("{ .reg .u64 t; cvta.to.shared.u64 t, %1; cvt.u32.u64 %0, t; }" : "=r"(a) : "l"(p));
    return a;
}
__device__ __forceinline__ void ldsm4(uint32_t r[4], uint32_t a) {
    asm volatile("ldmatrix.sync.aligned.m8n8.x4.shared.b16 {%0,%1,%2,%3}, [%4];"
                 : "=r"(r[0]), "=r"(r[1]), "=r"(r[2]), "=r"(r[3]) : "r"(a));
}
__device__ __forceinline__ void ldsm4t(uint32_t r[4], uint32_t a) {
    asm volatile("ldmatrix.sync.aligned.m8n8.x4.trans.shared.b16 {%0,%1,%2,%3}, [%4];"
                 : "=r"(r[0]), "=r"(r[1]), "=r"(r[2]), "=r"(r[3]) : "r"(a));
}
__device__ __forceinline__ void mmab(float c[4], const uint32_t a[4], uint32_t b0, uint32_t b1) {
    asm volatile("mma.sync.aligned.m16n8k16.row.col.f32.bf16.bf16.f32 "
                 "{%0,%1,%2,%3}, {%4,%5,%6,%7}, {%8,%9}, {%0,%1,%2,%3};"
                 : "+f"(c[0]), "+f"(c[1]), "+f"(c[2]), "+f"(c[3])
                 : "r"(a[0]), "r"(a[1]), "r"(a[2]), "r"(a[3]), "r"(b0), "r"(b1));
}
__device__ __forceinline__ uint32_t pkbf(__nv_bfloat16 a, __nv_bfloat16 b) {
    __nv_bfloat162 t(a, b);
    return *(uint32_t*)&t;
}
#define CPA16(dst, src) \
    asm volatile("cp.async.cg.shared.global [%0], [%1], 16;" :: "r"(dst), "l"(src) : "memory")
#define CPA_COMMIT() asm volatile("cp.async.commit_group;" ::: "memory")
#define CPA_WAIT0()  asm volatile("cp.async.wait_group 0;" ::: "memory")

// ---- pre-pass: fp32 -> bf16 hi/lo split for Q (scaled), K, V ----
__device__ __forceinline__ void split4(float4 x, uint2& hi, uint2& lo) {
    __nv_bfloat16 h0 = __float2bfloat16(x.x), h1 = __float2bfloat16(x.y);
    __nv_bfloat16 h2 = __float2bfloat16(x.z), h3 = __float2bfloat16(x.w);
    hi = make_uint2(pkbf(h0, h1), pkbf(h2, h3));
    lo = make_uint2(pkbf(__float2bfloat16(x.x - __bfloat162float(h0)),
                         __float2bfloat16(x.y - __bfloat162float(h1))),
                    pkbf(__float2bfloat16(x.z - __bfloat162float(h2)),
                         __float2bfloat16(x.w - __bfloat162float(h3))));
}
__global__ void convert_kernel(const float* __restrict__ Q, const float* __restrict__ K,
                               const float* __restrict__ V)
{
    long i = (long)blockIdx.x * blockDim.x + threadIdx.x;
    if (i >= NELEM / 4) return;
    long e = i * 4;
    uint2 hi, lo;
    float4 q = *(const float4*)&Q[e];
    q.x *= 0.125f; q.y *= 0.125f; q.z *= 0.125f; q.w *= 0.125f;
    split4(q, hi, lo);
    *(uint2*)&g_qh[e] = hi; *(uint2*)&g_ql[e] = lo;
    split4(*(const float4*)&K[e], hi, lo);
    *(uint2*)&g_kh[e] = hi; *(uint2*)&g_kl[e] = lo;
    split4(*(const float4*)&V[e], hi, lo);
    *(uint2*)&g_vh[e] = hi; *(uint2*)&g_vl[e] = lo;
}

__device__ __forceinline__ void cpa_tile(uint32_t dstbase, const __nv_bfloat16* src, int tid) {
    #pragma unroll
    for (int i = tid; i < TILE_CHUNKS; i += NTHR) {
        int r = i >> 3, c8 = i & 7;
        CPA16(dstbase + r * STRB + c8 * 16, src + (long)r * DD + c8 * 8);
    }
}

// S for this warp's 16 rows x 64-col half: acc[8 n-tiles][4], 3-term bf16
__device__ __forceinline__ void compute_S_half(float acc[8][4], uint32_t qhA, uint32_t qlA,
                                               uint32_t khB, uint32_t klB)
{
    #pragma unroll
    for (int j = 0; j < 8; j++)
        #pragma unroll
        for (int i = 0; i < 4; i++) acc[j][i] = 0.0f;
    #pragma unroll
    for (int s = 0; s < 4; s++) {
        uint32_t aH[4], aL[4];
        ldsm4(aH, qhA + s * 32);
        ldsm4(aL, qlA + s * 32);
        #pragma unroll
        for (int jp = 0; jp < 4; jp++) {
            uint32_t bH[4], bL[4];
            ldsm4(bH, khB + jp * (16 * STRB) + s * 32);
            ldsm4(bL, klB + jp * (16 * STRB) + s * 32);
            mmab(acc[2 * jp],     aH, bH[0], bH[1]);
            mmab(acc[2 * jp + 1], aH, bH[2], bH[3]);
            mmab(acc[2 * jp],     aH, bL[0], bL[1]);
            mmab(acc[2 * jp + 1], aH, bL[2], bL[3]);
            mmab(acc[2 * jp],     aL, bH[0], bH[1]);
            mmab(acc[2 * jp + 1], aL, bH[2], bH[3]);
        }
    }
}

__global__ __launch_bounds__(NTHR, 1)
void fa_mma_kernel(const int* __restrict__ mask,
                   float* __restrict__ out_o, float* __restrict__ out_p)
{
    extern __shared__ char sm[];
    const uint32_t sb = s2u(sm);
    const int tid = threadIdx.x, wid = tid >> 5, lane = tid & 31;
    const int qg = wid & 7, cg = wid >> 3;
    const int q0 = qg * 16;

    const int qtile = blockIdx.x, h = blockIdx.y, b = blockIdx.z;
    const long bh = (long)(b * HH + h);
    const long qbase = bh * SS + (long)qtile * QB;
    const long kvbase = bh * SS;

    // ---- prologue: Q tiles + mask + chunk 0, one cp.async group ----
    cpa_tile(sb + OFF_QH, g_qh + qbase * DD, tid);
    cpa_tile(sb + OFF_QL, g_ql + qbase * DD, tid);
    if (tid < 512) CPA16(sb + OFF_MSK + tid * 16, mask + (long)b * SS + tid * 4);
    cpa_tile(sb + ST_OFF(0, 0), g_kh + kvbase * DD, tid);
    cpa_tile(sb + ST_OFF(0, 1), g_kl + kvbase * DD, tid);
    cpa_tile(sb + ST_OFF(0, 2), g_vh + kvbase * DD, tid);
    cpa_tile(sb + ST_OFF(0, 3), g_vl + kvbase * DD, tid);
    CPA_COMMIT();

    const uint32_t kbase = (uint32_t)cg * 64 * STRB;
    const uint32_t aoff = (uint32_t)(q0 + (lane & 15)) * STRB + ((lane >> 4) & 1) * 16;
    const uint32_t koff = kbase + (uint32_t)((lane & 7) + ((lane & 16) ? 8 : 0)) * STRB
                        + ((lane & 8) ? 16 : 0);
    const uint32_t voff = kbase + (uint32_t)(lane & 15) * STRB + ((lane >> 4) & 1) * 16;

    int* msk = (int*)(sm + OFF_MSK);
    float oacc[8][4];
    #pragma unroll
    for (int j = 0; j < 8; j++)
        #pragma unroll
        for (int i = 0; i < 4; i++) oacc[j][i] = 0.0f;
    float rs0 = 0.0f, rs1 = 0.0f;

    // ================= Pass 1: S -> fused {exp/pack | PV-MMA} per k16-step ==========
    for (int ch = 0; ch < NCHUNK; ch++) {
        const int st = ch & 1;
        CPA_WAIT0();
        __syncthreads();
        if (ch + 1 < NCHUNK) {
            const long nb = (kvbase + (long)(ch + 1) * NC) * DD;
            const int ns = st ^ 1;
            cpa_tile(sb + ST_OFF(ns, 0), g_kh + nb, tid);
            cpa_tile(sb + ST_OFF(ns, 1), g_kl + nb, tid);
            cpa_tile(sb + ST_OFF(ns, 2), g_vh + nb, tid);
            cpa_tile(sb + ST_OFF(ns, 3), g_vl + nb, tid);
            CPA_COMMIT();
        }

        float acc[8][4];
        compute_S_half(acc, sb + OFF_QH + aoff, sb + OFF_QL + aoff,
                       sb + ST_OFF(st, 0) + koff, sb + ST_OFF(st, 1) + koff);

        const uint32_t vh = sb + ST_OFF(st, 2) + voff, vl = sb + ST_OFF(st, 3) + voff;
        // fused epilogue+PV: exp/pack for step s issues while PV HMMAs of step s-1 drain
        #pragma unroll
        for (int s = 0; s < 4; s++) {
            uint32_t PH[4], PL[4];
            #pragma unroll
            for (int hf = 0; hf < 2; hf++) {
                const int jt = 2 * s + hf;
                int colb = ch * NC + cg * 64 + 8 * jt + 2 * (lane & 3);
                int2 mm = *(const int2*)&msk[colb];
                float m0 = mm.x ? 1.0f : 0.0f, m1 = mm.y ? 1.0f : 0.0f;
                float e0 = __expf(acc[jt][0]) * m0, e1 = __expf(acc[jt][1]) * m1;
                float e2 = __expf(acc[jt][2]) * m0, e3 = __expf(acc[jt][3]) * m1;
                rs0 += e0 + e1; rs1 += e2 + e3;
                __nv_bfloat16 h0 = __float2bfloat16(e0), h1 = __float2bfloat16(e1);
                __nv_bfloat16 h2 = __float2bfloat16(e2), h3 = __float2bfloat16(e3);
                float l0 = e0 - __bfloat162float(h0), l1 = e1 - __bfloat162float(h1);
                float l2 = e2 - __bfloat162float(h2), l3 = e3 - __bfloat162float(h3);
                PH[2 * hf]     = pkbf(h0, h1);
                PH[2 * hf + 1] = pkbf(h2, h3);
                PL[2 * hf]     = pkbf(__float2bfloat16(l0), __float2bfloat16(l1));
                PL[2 * hf + 1] = pkbf(__float2bfloat16(l2), __float2bfloat16(l3));
            }
            #pragma unroll
            for (int dp = 0; dp < 4; dp++) {
                uint32_t vH[4], vL[4];
                ldsm4t(vH, vh + s * (16 * STRB) + dp * 32);
                ldsm4t(vL, vl + s * (16 * STRB) + dp * 32);
                mmab(oacc[2 * dp],     PH, vH[0], vH[1]);
                mmab(oacc[2 * dp + 1], PH, vH[2], vH[3]);
                mmab(oacc[2 * dp],     PH, vL[0], vL[1]);
                mmab(oacc[2 * dp + 1], PH, vL[2], vL[3]);
                mmab(oacc[2 * dp],     PL, vH[0], vH[1]);
                mmab(oacc[2 * dp + 1], PL, vH[2], vH[3]);
            }
        }
    }

    __syncthreads();   // all pass-1 compute done (stages free)

    // prefetch pass-2 chunk 0 — overlaps rowsum + O reduction
    cpa_tile(sb + ST_OFF(0, 0), g_kh + kvbase * DD, tid);
    cpa_tile(sb + ST_OFF(0, 1), g_kl + kvbase * DD, tid);
    CPA_COMMIT();

    // ---- row sums ----
    rs0 += __shfl_xor_sync(0xffffffffu, rs0, 1);
    rs0 += __shfl_xor_sync(0xffffffffu, rs0, 2);
    rs1 += __shfl_xor_sync(0xffffffffu, rs1, 1);
    rs1 += __shfl_xor_sync(0xffffffffu, rs1, 2);
    float* l2p = (float*)(sm + OFF_L2);
    if ((lane & 3) == 0) {
        l2p[2 * (q0 + (lane >> 2)) + cg]     = rs0;
        l2p[2 * (q0 + 8 + (lane >> 2)) + cg] = rs1;
    }
    __syncthreads();
    const float il0 = 1.0f / (l2p[2 * (q0 + (lane >> 2))] + l2p[2 * (q0 + (lane >> 2)) + 1]);
    const float il1 = 1.0f / (l2p[2 * (q0 + 8 + (lane >> 2))] + l2p[2 * (q0 + 8 + (lane >> 2)) + 1]);

    // ---- O cross-half reduction ----
    float* stg = (float*)(sm + OFF_OST);
    const int rlo = q0 + (lane >> 2), rhi = rlo + 8;
    if (cg == 1) {
        #pragma unroll
        for (int nt = 0; nt < 8; nt++) {
            int c = 8 * nt + 2 * (lane & 3);
            *(float2*)&stg[rlo * 64 + c] = make_float2(oacc[nt][0], oacc[nt][1]);
            *(float2*)&stg[rhi * 64 + c] = make_float2(oacc[nt][2], oacc[nt][3]);
        }
    }
    __syncthreads();
    const long row0 = qbase + q0 + (lane >> 2);
    if (cg == 0) {
        #pragma unroll
        for (int nt = 0; nt < 8; nt++) {
            int c = 8 * nt + 2 * (lane & 3);
            float2 s0 = *(const float2*)&stg[rlo * 64 + c];
            float2 s1 = *(const float2*)&stg[rhi * 64 + c];
            *(float2*)&out_o[row0 * DD + c] =
                make_float2((oacc[nt][0] + s0.x) * il0, (oacc[nt][1] + s0.y) * il0);
            *(float2*)&out_o[(row0 + 8) * DD + c] =
                make_float2((oacc[nt][2] + s1.x) * il1, (oacc[nt][3] + s1.y) * il1);
        }
    }

    // ================= Pass 2: recompute S, write normalized probs =================
    for (int ch = 0; ch < NCHUNK; ch++) {
        const int st = ch & 1;
        CPA_WAIT0();
        __syncthreads();
        if (ch + 1 < NCHUNK) {
            const long nb = (kvbase + (long)(ch + 1) * NC) * DD;
            const int ns = st ^ 1;
            cpa_tile(sb + ST_OFF(ns, 0), g_kh + nb, tid);
            cpa_tile(sb + ST_OFF(ns, 1), g_kl + nb, tid);
            CPA_COMMIT();
        }

        float acc[8][4];
        compute_S_half(acc, sb + OFF_QH + aoff, sb + OFF_QL + aoff,
                       sb + ST_OFF(st, 0) + koff, sb + ST_OFF(st, 1) + koff);

        #pragma unroll
        for (int jt = 0; jt < 8; jt++) {
            int colb = ch * NC + cg * 64 + 8 * jt + 2 * (lane & 3);
            int2 mm = *(const int2*)&msk[colb];
            float m0 = mm.x ? il0 : 0.0f, m1 = mm.y ? il0 : 0.0f;
            float n0 = mm.x ? il1 : 0.0f, n1 = mm.y ? il1 : 0.0f;
            *(float2*)&out_p[row0 * SS + colb] =
                make_float2(__expf(acc[jt][0]) * m0, __expf(acc[jt][1]) * m1);
            *(float2*)&out_p[(row0 + 8) * SS + colb] =
                make_float2(__expf(acc[jt][2]) * n0, __expf(acc[jt][3]) * n1);
        }
    }
}

extern "C" void kernel_launch(void* const* d_in, const int* in_sizes, int n_in,
                              void* d_out, int out_size)
{
    const float* Q    = (const float*)d_in[0];
    const float* K    = (const float*)d_in[1];
    const float* V    = (const float*)d_in[2];
    const int*   mask = (const int*)d_in[3];

    float* out_o = (float*)d_out;                       // [B,H,S,D]
    float* out_p = out_o + (size_t)BB * HH * SS * DD;   // [B,H,S,S]

    convert_kernel<<<NELEM / 4 / 256, 256>>>(Q, K, V);

    cudaFuncSetAttribute(fa_mma_kernel,
                         cudaFuncAttributeMaxDynamicSharedMemorySize, SMEM_TOTAL);
    dim3 grid(SS / QB, HH, BB);   // (16, 16, 2) = 512 CTAs
    fa_mma_kernel<<<grid, NTHR, SMEM_TOTAL>>>(mask, out_o, out_p);
}

// round 8
// speedup vs baseline: 1.2916x; 1.1090x over previous
#include <cuda_runtime.h>
#include <cuda_bf16.h>
#include <stdint.h>

// ScaledDotProductAttention: B=2, H=16, S=2048, D=64, scale=8
#define BB 2
#define HH 16
#define SS 2048
#define DD 64
#define QB 64             // q rows per CTA
#define NC 64             // k cols per chunk
#define NCHUNK (SS / NC)  // 32
#define NTHR 256          // 8 warps: 4 q-groups x 2 col-halves
#define NELEM (BB * HH * SS * DD)   // 4,194,304

#define STRB 144                 // smem row stride bytes (72 bf16, ldmatrix conflict-free)
#define TILEB (64 * STRB)        // 9216 B per [64 x 64] bf16 tile
#define TILE_CHUNKS 512          // 16B chunks per tile (64 rows x 8)

#define OFF_QH 0
#define OFF_QL TILEB
#define OFF_STAGE (2 * TILEB)                 // 8 tiles: stage{0,1} x {KH,KL,VH,VL}
#define ST_OFF(st, t) (OFF_STAGE + ((st) * 4 + (t)) * TILEB)
#define OFF_OST (OFF_STAGE + 2 * TILEB)       // O fp32 stage (16KB) over VH0+VL0
#define OFF_MSK (OFF_STAGE + 8 * TILEB)       // int[2048]
#define OFF_L2  (OFF_MSK + SS * 4)            // float[64][2]
#define SMEM_TOTAL (OFF_L2 + 64 * 2 * 4)      // 100864 B -> 2 CTAs/SM

// pre-converted bf16 hi/lo tensors (Q pre-scaled by 1/8)
__device__ __nv_bfloat16 g_qh[NELEM], g_ql[NELEM];
__device__ __nv_bfloat16 g_kh[NELEM], g_kl[NELEM];
__device__ __nv_bfloat16 g_vh[NELEM], g_vl[NELEM];

__device__ __forceinline__ uint32_t s2u(const void* p) {
    uint32_t a;
    asm("{ .reg .u64 t; cvta.to.shared.u64 t, %1; cvt.u32.u64 %0, t; }" : "=r"(a) : "l"(p));
    return a;
}
__device__ __forceinline__ void ldsm4(uint32_t r[4], uint32_t a) {
    asm volatile("ldmatrix.sync.aligned.m8n8.x4.shared.b16 {%0,%1,%2,%3}, [%4];"
                 : "=r"(r[0]), "=r"(r[1]), "=r"(r[2]), "=r"(r[3]) : "r"(a));
}
__device__ __forceinline__ void ldsm4t(uint32_t r[4], uint32_t a) {
    asm volatile("ldmatrix.sync.aligned.m8n8.x4.trans.shared.b16 {%0,%1,%2,%3}, [%4];"
                 : "=r"(r[0]), "=r"(r[1]), "=r"(r[2]), "=r"(r[3]) : "r"(a));
}
__device__ __forceinline__ void mmab(float c[4], const uint32_t a[4], uint32_t b0, uint32_t b1) {
    asm volatile("mma.sync.aligned.m16n8k16.row.col.f32.bf16.bf16.f32 "
                 "{%0,%1,%2,%3}, {%4,%5,%6,%7}, {%8,%9}, {%0,%1,%2,%3};"
                 : "+f"(c[0]), "+f"(c[1]), "+f"(c[2]), "+f"(c[3])
                 : "r"(a[0]), "r"(a[1]), "r"(a[2]), "r"(a[3]), "r"(b0), "r"(b1));
}
__device__ __forceinline__ uint32_t pkbf(__nv_bfloat16 a, __nv_bfloat16 b) {
    __nv_bfloat162 t(a, b);
    return *(uint32_t*)&t;
}
#define CPA16(dst, src) \
    asm volatile("cp.async.cg.shared.global [%0], [%1], 16;" :: "r"(dst), "l"(src) : "memory")
#define CPA_COMMIT() asm volatile("cp.async.commit_group;" ::: "memory")
#define CPA_WAIT0()  asm volatile("cp.async.wait_group 0;" ::: "memory")

// ---- pre-pass: fp32 -> bf16 hi/lo split for Q (scaled), K, V ----
__device__ __forceinline__ void split4(float4 x, uint2& hi, uint2& lo) {
    __nv_bfloat16 h0 = __float2bfloat16(x.x), h1 = __float2bfloat16(x.y);
    __nv_bfloat16 h2 = __float2bfloat16(x.z), h3 = __float2bfloat16(x.w);
    hi = make_uint2(pkbf(h0, h1), pkbf(h2, h3));
    lo = make_uint2(pkbf(__float2bfloat16(x.x - __bfloat162float(h0)),
                         __float2bfloat16(x.y - __bfloat162float(h1))),
                    pkbf(__float2bfloat16(x.z - __bfloat162float(h2)),
                         __float2bfloat16(x.w - __bfloat162float(h3))));
}
__global__ void convert_kernel(const float* __restrict__ Q, const float* __restrict__ K,
                               const float* __restrict__ V)
{
    long i = (long)blockIdx.x * blockDim.x + threadIdx.x;
    if (i >= NELEM / 4) return;
    long e = i * 4;
    uint2 hi, lo;
    float4 q = *(const float4*)&Q[e];
    q.x *= 0.125f; q.y *= 0.125f; q.z *= 0.125f; q.w *= 0.125f;
    split4(q, hi, lo);
    *(uint2*)&g_qh[e] = hi; *(uint2*)&g_ql[e] = lo;
    split4(*(const float4*)&K[e], hi, lo);
    *(uint2*)&g_kh[e] = hi; *(uint2*)&g_kl[e] = lo;
    split4(*(const float4*)&V[e], hi, lo);
    *(uint2*)&g_vh[e] = hi; *(uint2*)&g_vl[e] = lo;
}

// cp.async a [64 x 64] bf16 tile (gmem row-major) into stride-144 smem
__device__ __forceinline__ void cpa_tile(uint32_t dstbase, const __nv_bfloat16* src, int tid) {
    #pragma unroll
    for (int i = tid; i < TILE_CHUNKS; i += NTHR) {
        int r = i >> 3, c8 = i & 7;
        CPA16(dstbase + r * STRB + c8 * 16, src + (long)r * DD + c8 * 8);
    }
}

// S for this warp's 16 rows x 32-col half: acc[4 n-tiles][4], 3-term bf16
__device__ __forceinline__ void compute_S_half(float acc[4][4], uint32_t qhA, uint32_t qlA,
                                               uint32_t khB, uint32_t klB)
{
    #pragma unroll
    for (int j = 0; j < 4; j++)
        #pragma unroll
        for (int i = 0; i < 4; i++) acc[j][i] = 0.0f;
    #pragma unroll
    for (int s = 0; s < 4; s++) {
        uint32_t aH[4], aL[4];
        ldsm4(aH, qhA + s * 32);
        ldsm4(aL, qlA + s * 32);
        #pragma unroll
        for (int jp = 0; jp < 2; jp++) {
            uint32_t bH[4], bL[4];
            ldsm4(bH, khB + jp * (16 * STRB) + s * 32);
            ldsm4(bL, klB + jp * (16 * STRB) + s * 32);
            mmab(acc[2 * jp],     aH, bH[0], bH[1]);
            mmab(acc[2 * jp + 1], aH, bH[2], bH[3]);
            mmab(acc[2 * jp],     aH, bL[0], bL[1]);
            mmab(acc[2 * jp + 1], aH, bL[2], bL[3]);
            mmab(acc[2 * jp],     aL, bH[0], bH[1]);
            mmab(acc[2 * jp + 1], aL, bH[2], bH[3]);
        }
    }
}

__global__ __launch_bounds__(NTHR, 2)
void fa_mma_kernel(const int* __restrict__ mask,
                   float* __restrict__ out_o, float* __restrict__ out_p)
{
    extern __shared__ char sm[];
    const uint32_t sb = s2u(sm);
    const int tid = threadIdx.x, wid = tid >> 5, lane = tid & 31;
    const int qg = wid & 3, cg = wid >> 2;
    const int q0 = qg * 16;

    const int qtile = blockIdx.x, h = blockIdx.y, b = blockIdx.z;
    const long bh = (long)(b * HH + h);
    const long qbase = bh * SS + (long)qtile * QB;
    const long kvbase = bh * SS;

    // ---- prologue: Q tiles + mask + chunk 0, one cp.async group ----
    cpa_tile(sb + OFF_QH, g_qh + qbase * DD, tid);
    cpa_tile(sb + OFF_QL, g_ql + qbase * DD, tid);
    #pragma unroll
    for (int i = tid; i < 512; i += NTHR)
        CPA16(sb + OFF_MSK + i * 16, mask + (long)b * SS + i * 4);
    cpa_tile(sb + ST_OFF(0, 0), g_kh + kvbase * DD, tid);
    cpa_tile(sb + ST_OFF(0, 1), g_kl + kvbase * DD, tid);
    cpa_tile(sb + ST_OFF(0, 2), g_vh + kvbase * DD, tid);
    cpa_tile(sb + ST_OFF(0, 3), g_vl + kvbase * DD, tid);
    CPA_COMMIT();

    // per-lane ldmatrix addresses (K/V tiles have 64 rows; warp uses its cg 32-row half)
    const uint32_t kvrow = (uint32_t)cg * 32 * STRB;
    const uint32_t aoff = (uint32_t)(q0 + (lane & 15)) * STRB + ((lane >> 4) & 1) * 16;
    const uint32_t koff = kvrow + (uint32_t)((lane & 7) + ((lane & 16) ? 8 : 0)) * STRB
                        + ((lane & 8) ? 16 : 0);
    const uint32_t voff = kvrow + (uint32_t)(lane & 15) * STRB + ((lane >> 4) & 1) * 16;

    int* msk = (int*)(sm + OFF_MSK);
    float oacc[8][4];
    #pragma unroll
    for (int j = 0; j < 8; j++)
        #pragma unroll
        for (int i = 0; i < 4; i++) oacc[j][i] = 0.0f;
    float rs0 = 0.0f, rs1 = 0.0f;

    // ================= Pass 1: partial rowsums + partial O (k-half per warp) ==========
    for (int ch = 0; ch < NCHUNK; ch++) {
        const int st = ch & 1;
        CPA_WAIT0();
        __syncthreads();
        if (ch + 1 < NCHUNK) {
            const long nb = (kvbase + (long)(ch + 1) * NC) * DD;
            const int ns = st ^ 1;
            cpa_tile(sb + ST_OFF(ns, 0), g_kh + nb, tid);
            cpa_tile(sb + ST_OFF(ns, 1), g_kl + nb, tid);
            cpa_tile(sb + ST_OFF(ns, 2), g_vh + nb, tid);
            cpa_tile(sb + ST_OFF(ns, 3), g_vl + nb, tid);
            CPA_COMMIT();
        }

        float acc[4][4];
        compute_S_half(acc, sb + OFF_QH + aoff, sb + OFF_QL + aoff,
                       sb + ST_OFF(st, 0) + koff, sb + ST_OFF(st, 1) + koff);

        const uint32_t vh = sb + ST_OFF(st, 2) + voff, vl = sb + ST_OFF(st, 3) + voff;
        // fused per-k16-step: exp/pack 2 n-tiles, then PV MMAs for that step
        #pragma unroll
        for (int s = 0; s < 2; s++) {
            uint32_t PH[4], PL[4];
            #pragma unroll
            for (int hf = 0; hf < 2; hf++) {
                const int jt = 2 * s + hf;
                int colb = ch * NC + cg * 32 + 8 * jt + 2 * (lane & 3);
                int2 mm = *(const int2*)&msk[colb];
                float m0 = mm.x ? 1.0f : 0.0f, m1 = mm.y ? 1.0f : 0.0f;
                float e0 = __expf(acc[jt][0]) * m0, e1 = __expf(acc[jt][1]) * m1;
                float e2 = __expf(acc[jt][2]) * m0, e3 = __expf(acc[jt][3]) * m1;
                rs0 += e0 + e1; rs1 += e2 + e3;
                __nv_bfloat16 h0 = __float2bfloat16(e0), h1 = __float2bfloat16(e1);
                __nv_bfloat16 h2 = __float2bfloat16(e2), h3 = __float2bfloat16(e3);
                float l0 = e0 - __bfloat162float(h0), l1 = e1 - __bfloat162float(h1);
                float l2 = e2 - __bfloat162float(h2), l3 = e3 - __bfloat162float(h3);
                PH[2 * hf]     = pkbf(h0, h1);
                PH[2 * hf + 1] = pkbf(h2, h3);
                PL[2 * hf]     = pkbf(__float2bfloat16(l0), __float2bfloat16(l1));
                PL[2 * hf + 1] = pkbf(__float2bfloat16(l2), __float2bfloat16(l3));
            }
            #pragma unroll
            for (int dp = 0; dp < 4; dp++) {
                uint32_t vH[4], vL[4];
                ldsm4t(vH, vh + s * (16 * STRB) + dp * 32);
                ldsm4t(vL, vl + s * (16 * STRB) + dp * 32);
                mmab(oacc[2 * dp],     PH, vH[0], vH[1]);
                mmab(oacc[2 * dp + 1], PH, vH[2], vH[3]);
                mmab(oacc[2 * dp],     PH, vL[0], vL[1]);
                mmab(oacc[2 * dp + 1], PH, vL[2], vL[3]);
                mmab(oacc[2 * dp],     PL, vH[0], vH[1]);
                mmab(oacc[2 * dp + 1], PL, vH[2], vH[3]);
            }
        }
    }

    __syncthreads();   // all pass-1 compute done (stages free)

    // prefetch pass-2 chunk 0 — overlaps rowsum + O reduction
    cpa_tile(sb + ST_OFF(0, 0), g_kh + kvbase * DD, tid);
    cpa_tile(sb + ST_OFF(0, 1), g_kl + kvbase * DD, tid);
    CPA_COMMIT();

    // ---- row sums: intra-warp then cross-half via smem ----
    rs0 += __shfl_xor_sync(0xffffffffu, rs0, 1);
    rs0 += __shfl_xor_sync(0xffffffffu, rs0, 2);
    rs1 += __shfl_xor_sync(0xffffffffu, rs1, 1);
    rs1 += __shfl_xor_sync(0xffffffffu, rs1, 2);
    float* l2p = (float*)(sm + OFF_L2);
    if ((lane & 3) == 0) {
        l2p[2 * (q0 + (lane >> 2)) + cg]     = rs0;
        l2p[2 * (q0 + 8 + (lane >> 2)) + cg] = rs1;
    }
    __syncthreads();
    const float il0 = 1.0f / (l2p[2 * (q0 + (lane >> 2))] + l2p[2 * (q0 + (lane >> 2)) + 1]);
    const float il1 = 1.0f / (l2p[2 * (q0 + 8 + (lane >> 2))] + l2p[2 * (q0 + 8 + (lane >> 2)) + 1]);

    // ---- O cross-half reduction through fp32 stage (VH0/VL0 region) ----
    float* stg = (float*)(sm + OFF_OST);
    const int rlo = q0 + (lane >> 2), rhi = rlo + 8;
    if (cg == 1) {
        #pragma unroll
        for (int nt = 0; nt < 8; nt++) {
            int c = 8 * nt + 2 * (lane & 3);
            *(float2*)&stg[rlo * 64 + c] = make_float2(oacc[nt][0], oacc[nt][1]);
            *(float2*)&stg[rhi * 64 + c] = make_float2(oacc[nt][2], oacc[nt][3]);
        }
    }
    __syncthreads();
    const long row0 = qbase + q0 + (lane >> 2);
    if (cg == 0) {
        #pragma unroll
        for (int nt = 0; nt < 8; nt++) {
            int c = 8 * nt + 2 * (lane & 3);
            float2 s0 = *(const float2*)&stg[rlo * 64 + c];
            float2 s1 = *(const float2*)&stg[rhi * 64 + c];
            *(float2*)&out_o[row0 * DD + c] =
                make_float2((oacc[nt][0] + s0.x) * il0, (oacc[nt][1] + s0.y) * il0);
            *(float2*)&out_o[(row0 + 8) * DD + c] =
                make_float2((oacc[nt][2] + s1.x) * il1, (oacc[nt][3] + s1.y) * il1);
        }
    }

    // ================= Pass 2: recompute S, write normalized probs =================
    for (int ch = 0; ch < NCHUNK; ch++) {
        const int st = ch & 1;
        CPA_WAIT0();
        __syncthreads();
        if (ch + 1 < NCHUNK) {
            const long nb = (kvbase + (long)(ch + 1) * NC) * DD;
            const int ns = st ^ 1;
            cpa_tile(sb + ST_OFF(ns, 0), g_kh + nb, tid);
            cpa_tile(sb + ST_OFF(ns, 1), g_kl + nb, tid);
            CPA_COMMIT();
        }

        float acc[4][4];
        compute_S_half(acc, sb + OFF_QH + aoff, sb + OFF_QL + aoff,
                       sb + ST_OFF(st, 0) + koff, sb + ST_OFF(st, 1) + koff);

        #pragma unroll
        for (int jt = 0; jt < 4; jt++) {
            int colb = ch * NC + cg * 32 + 8 * jt + 2 * (lane & 3);
            int2 mm = *(const int2*)&msk[colb];
            float m0 = mm.x ? il0 : 0.0f, m1 = mm.y ? il0 : 0.0f;
            float n0 = mm.x ? il1 : 0.0f, n1 = mm.y ? il1 : 0.0f;
            *(float2*)&out_p[row0 * SS + colb] =
                make_float2(__expf(acc[jt][0]) * m0, __expf(acc[jt][1]) * m1);
            *(float2*)&out_p[(row0 + 8) * SS + colb] =
                make_float2(__expf(acc[jt][2]) * n0, __expf(acc[jt][3]) * n1);
        }
    }
}

extern "C" void kernel_launch(void* const* d_in, const int* in_sizes, int n_in,
                              void* d_out, int out_size)
{
    const float* Q    = (const float*)d_in[0];
    const float* K    = (const float*)d_in[1];
    const float* V    = (const float*)d_in[2];
    const int*   mask = (const int*)d_in[3];

    float* out_o = (float*)d_out;                       // [B,H,S,D]
    float* out_p = out_o + (size_t)BB * HH * SS * DD;   // [B,H,S,S]

    convert_kernel<<<NELEM / 4 / 256, 256>>>(Q, K, V);

    cudaFuncSetAttribute(fa_mma_kernel,
                         cudaFuncAttributeMaxDynamicSharedMemorySize, SMEM_TOTAL);
    dim3 grid(SS / QB, HH, BB);   // (32, 16, 2) = 1024 CTAs, 2 per SM
    fa_mma_kernel<<<grid, NTHR, SMEM_TOTAL>>>(mask, out_o, out_p);
}